// round 12
// baseline (speedup 1.0000x reference)
#include <cuda_runtime.h>
#include <cuda_fp16.h>
#include <cstdint>

// Problem constants
constexpr int DM   = 1024;   // d_model
constexpr int NH   = 16;     // heads
constexpr int DQ   = 64;     // d_qkv
constexpr int NB   = 2;      // batch
constexpr int NL   = 2048;   // seq len
constexpr int ROWS = NB * NL;            // 4096
constexpr float LN_EPS = 1e-5f;
// Q prescale: 1/sqrt(64) * log2(e)  (folded into W_q at prep)
constexpr float QS = 0.125f * 1.4426950408889634f;
// uniform softmax bias: P = 2^(s-SB) <= ~2^11 fits fp16; cancels in normalize
constexpr float SB = 4.0f;

// Scratch (static device globals: no allocations allowed)
__device__ half  g_x_h[ROWS * DM];              // x as half [m][k]
__device__ half  g_wqkv_h[3][DM * DM];          // qkv weights TRANSPOSED: [t][n][k], QS folded for t=0
__device__ half  g_wo_h[DM * DM];               // wo TRANSPOSED: [n][k]
__device__ half  g_qkv_h[3][NB * NH][NL][DQ];   // Q(prescaled), K, V  (half)
__device__ half  g_att_h[ROWS * DM];            // attention out, [B,L,H*dq] half
__device__ float g_proj[ROWS][DM];              // output projection result

__device__ __forceinline__ uint32_t smem_u32(const void* p) {
    uint32_t a;
    asm("{ .reg .u64 t; cvta.to.shared.u64 t, %1; cvt.u32.u64 %0, t; }" : "=r"(a) : "l"(p));
    return a;
}
__device__ __forceinline__ void cp16(uint32_t dst, const void* src) {
    asm volatile("cp.async.cg.shared.global [%0], [%1], 16;" :: "r"(dst), "l"(src));
}
#define CP_COMMIT() asm volatile("cp.async.commit_group;" ::: "memory")
#define CP_WAIT0()  asm volatile("cp.async.wait_group 0;" ::: "memory")

__device__ __forceinline__ void ldsm4(uint32_t* r, uint32_t addr) {
    asm volatile("ldmatrix.sync.aligned.m8n8.x4.shared.b16 {%0,%1,%2,%3}, [%4];"
                 : "=r"(r[0]), "=r"(r[1]), "=r"(r[2]), "=r"(r[3]) : "r"(addr));
}
__device__ __forceinline__ void ldsm4t(uint32_t* r, uint32_t addr) {
    asm volatile("ldmatrix.sync.aligned.m8n8.x4.trans.shared.b16 {%0,%1,%2,%3}, [%4];"
                 : "=r"(r[0]), "=r"(r[1]), "=r"(r[2]), "=r"(r[3]) : "r"(addr));
}
__device__ __forceinline__ void mma16816(float* c, const uint32_t* a, uint32_t b0, uint32_t b1) {
    asm volatile("mma.sync.aligned.m16n8k16.row.col.f32.f16.f16.f32 "
                 "{%0,%1,%2,%3}, {%4,%5,%6,%7}, {%8,%9}, {%0,%1,%2,%3};"
                 : "+f"(c[0]), "+f"(c[1]), "+f"(c[2]), "+f"(c[3])
                 : "r"(a[0]), "r"(a[1]), "r"(a[2]), "r"(a[3]), "r"(b0), "r"(b1));
}
__device__ __forceinline__ uint32_t pack_h2(float a, float b) {
    half2 h = __floats2half2_rn(a, b);
    return *(uint32_t*)&h;
}

// SMEM sizes (dynamic)
// GEMM: A[2 stages][128][72] + B[2 stages][128][72] halves = 4 * 18432 B
constexpr int GEMM_SMEM = 4 * 18432;                                   // 73728 B
constexpr int ATT_SMEM  = (128 * 72 + 2 * 64 * 72 + 2 * 64 * 72) * 2;  // 55296 B

// ---------------------------------------------------------------------------
// Prep kernels
// ---------------------------------------------------------------------------
__global__ __launch_bounds__(256) void prep_x_kernel(const float* __restrict__ x) {
    const int i = (blockIdx.x * 256 + threadIdx.x) * 4;
    float4 v = *(const float4*)(x + i);
    half2 a = __floats2half2_rn(v.x, v.y);
    half2 b = __floats2half2_rn(v.z, v.w);
    uint2 pk = { *(uint32_t*)&a, *(uint32_t*)&b };
    *(uint2*)(g_x_h + i) = pk;
}

// Transpose + convert qkv weights: g_wqkv_h[t][h*64+n][k] = w_t[h][k][n] * (t==0?QS:1)
__global__ void prep_wqkv_kernel(const float* __restrict__ wq,
                                 const float* __restrict__ wk,
                                 const float* __restrict__ wv) {
    __shared__ float tile[32][33];
    const int z = blockIdx.z, t = z >> 4, h = z & 15;
    const float* __restrict__ in =
        (t == 0 ? wq : (t == 1 ? wk : wv)) + (size_t)h * DM * DQ;
    const float scale = (t == 0) ? QS : 1.0f;
    const int n0 = blockIdx.x * 32;       // 0 or 32 within head
    const int k0 = blockIdx.y * 32;
    const int tx = threadIdx.x, ty = threadIdx.y;    // (32, 8)
    #pragma unroll
    for (int i = 0; i < 4; ++i)           // tile[k_local][n_local]
        tile[ty + 8 * i][tx] = in[(size_t)(k0 + ty + 8 * i) * DQ + n0 + tx];
    __syncthreads();
    #pragma unroll
    for (int i = 0; i < 4; ++i) {         // out[n][k], k contiguous per thread row
        float v = tile[tx][ty + 8 * i] * scale;   // = in[k0+tx][n0+ty+8i]
        g_wqkv_h[t][(size_t)(h * 64 + n0 + ty + 8 * i) * DM + k0 + tx] = __float2half(v);
    }
}

// Transpose + convert wo: g_wo_h[n][k] = wo[k][n]
__global__ void prep_wo_kernel(const float* __restrict__ wo) {
    __shared__ float tile[32][33];
    const int n0 = blockIdx.x * 32, k0 = blockIdx.y * 32;
    const int tx = threadIdx.x, ty = threadIdx.y;
    #pragma unroll
    for (int i = 0; i < 4; ++i)
        tile[ty + 8 * i][tx] = wo[(size_t)(k0 + ty + 8 * i) * DM + n0 + tx];
    __syncthreads();
    #pragma unroll
    for (int i = 0; i < 4; ++i) {
        float v = tile[tx][ty + 8 * i];
        g_wo_h[(size_t)(n0 + ty + 8 * i) * DM + k0 + tx] = __float2half(v);
    }
}

// ---------------------------------------------------------------------------
// Unified half GEMM: C[128x128 tile] = A[m][k] * B[n][k]^T, K=1024.
// 128 threads, 2x2 warps, 64x64 warp tile, raw mma16816 + ldsm4,
// cp.async 2-stage pipeline. mode 0: x * Wqkv -> g_qkv_h (scatter per head);
// mode 1: att * Wo -> g_proj (fp32).
// ---------------------------------------------------------------------------
__global__ __launch_bounds__(128, 2) void gemm_kernel(int mode) {
    extern __shared__ half hsm[];
    const uint32_t base = smem_u32(hsm);
    // layout: A0 @0, A1 @18432, B0 @36864, B1 @55296 (each [128][72] halves)

    const int rt = blockIdx.x, ct = blockIdx.y;
    const int r0 = rt * 128;
    const half* __restrict__ Ag;
    const half* __restrict__ Bg;
    int n0;
    if (mode == 0) { Ag = g_x_h;   Bg = g_wqkv_h[ct >> 3]; n0 = (ct & 7) * 128; }
    else           { Ag = g_att_h; Bg = g_wo_h;            n0 = ct * 128;       }

    const int tid = threadIdx.x;
    const int w = tid >> 5, lane = tid & 31;
    const int wm = w & 1, wn = w >> 1;           // 2x2 warp grid, 64x64 tiles
    const int sub = lane >> 3;
    const uint32_t laneoff =
        (uint32_t)((((sub & 1) * 8) + (lane & 7)) * 144 + (sub >> 1) * 16);

    auto load_tile = [&](int ch, int buf) {
        const int k0 = ch * 64;
        const uint32_t Ab = base + buf * 18432;
        const uint32_t Bb = base + 36864 + buf * 18432;
        #pragma unroll
        for (int p = 0; p < 8; ++p) {            // A: 128 rows x 64 k
            int idx = tid + p * 128;
            int r = idx >> 3, q = idx & 7;
            cp16(Ab + r * 144 + q * 16, Ag + (size_t)(r0 + r) * DM + k0 + q * 8);
        }
        #pragma unroll
        for (int p = 0; p < 8; ++p) {            // B: 128 n-rows x 64 k
            int idx = tid + p * 128;
            int r = idx >> 3, q = idx & 7;
            cp16(Bb + r * 144 + q * 16, Bg + (size_t)(n0 + r) * DM + k0 + q * 8);
        }
    };

    float c[4][8][4];
    #pragma unroll
    for (int mt = 0; mt < 4; ++mt)
        #pragma unroll
        for (int nt = 0; nt < 8; ++nt)
            #pragma unroll
            for (int e = 0; e < 4; ++e) c[mt][nt][e] = 0.0f;

    load_tile(0, 0);
    CP_COMMIT();

    for (int ch = 0; ch < 16; ++ch) {
        CP_WAIT0();
        __syncthreads();
        if (ch + 1 < 16) { load_tile(ch + 1, (ch + 1) & 1); CP_COMMIT(); }
        const uint32_t Ab = base + (ch & 1) * 18432 + (wm * 64) * 144;
        const uint32_t Bb = base + 36864 + (ch & 1) * 18432 + (wn * 64) * 144;
        #pragma unroll
        for (int kt = 0; kt < 4; ++kt) {
            uint32_t aa[4][4], bb[4][4];
            #pragma unroll
            for (int mt = 0; mt < 4; ++mt)
                ldsm4(aa[mt], Ab + mt * 16 * 144 + kt * 32 + laneoff);
            #pragma unroll
            for (int nt = 0; nt < 4; ++nt)
                ldsm4(bb[nt], Bb + nt * 16 * 144 + kt * 32 + laneoff);
            #pragma unroll
            for (int mt = 0; mt < 4; ++mt)
                #pragma unroll
                for (int nt = 0; nt < 4; ++nt) {
                    mma16816(c[mt][2 * nt],     aa[mt], bb[nt][0], bb[nt][2]);
                    mma16816(c[mt][2 * nt + 1], aa[mt], bb[nt][1], bb[nt][3]);
                }
        }
    }
    __syncthreads();

    const int g = lane >> 2, cq = lane & 3;

    if (mode == 1) {                 // direct fp32 stores (pairs are contiguous)
        #pragma unroll
        for (int mt = 0; mt < 4; ++mt)
            #pragma unroll
            for (int nt = 0; nt < 8; ++nt) {
                const int rr = r0 + wm * 64 + mt * 16 + g;
                const int cc = n0 + wn * 64 + nt * 8 + 2 * cq;
                *(float2*)(&g_proj[rr][cc])     = make_float2(c[mt][nt][0], c[mt][nt][1]);
                *(float2*)(&g_proj[rr + 8][cc]) = make_float2(c[mt][nt][2], c[mt][nt][3]);
            }
        return;
    }

    // mode 0: stage fp32 in smem, then convert to half and scatter per head
    float* st = (float*)hsm;         // [128][132] = 67584 B <= 73728
    #pragma unroll
    for (int mt = 0; mt < 4; ++mt)
        #pragma unroll
        for (int nt = 0; nt < 8; ++nt) {
            const int rr = wm * 64 + mt * 16 + g;
            const int cc = wn * 64 + nt * 8 + 2 * cq;
            *(float2*)(st + rr * 132 + cc)       = make_float2(c[mt][nt][0], c[mt][nt][1]);
            *(float2*)(st + (rr + 8) * 132 + cc) = make_float2(c[mt][nt][2], c[mt][nt][3]);
        }
    __syncthreads();

    const int t = ct >> 3;
    const int h0 = (ct & 7) * 2;
    #pragma unroll
    for (int p = 0; p < 16; ++p) {   // 128x128 elems, 8-half chunks
        int idx = tid + p * 128;
        int r = idx >> 4, q = idx & 15;          // col = q*8
        const float* s = st + r * 132 + q * 8;
        half2 a0 = __floats2half2_rn(s[0], s[1]);
        half2 a1 = __floats2half2_rn(s[2], s[3]);
        half2 a2 = __floats2half2_rn(s[4], s[5]);
        half2 a3 = __floats2half2_rn(s[6], s[7]);
        uint4 pack = { *(uint32_t*)&a0, *(uint32_t*)&a1, *(uint32_t*)&a2, *(uint32_t*)&a3 };
        const int gr = r0 + r;
        const int b = gr >> 11, l = gr & (NL - 1);
        *(uint4*)(&g_qkv_h[t][b * NH + h0 + (q >> 3)][l][(q & 7) * 8]) = pack;
    }
}

// ---------------------------------------------------------------------------
// Flash attention (unchanged from R8 best): Br=128, Bc=64, FA2-style
// register-resident softmax, no-max (bias in accumulator init), cp.async KV.
// ---------------------------------------------------------------------------
__global__ __launch_bounds__(256, 2) void attn_kernel()
{
    extern __shared__ half hsm[];
    const uint32_t base = smem_u32(hsm);
    const uint32_t qsb = base;            // Q [128][72] halves
    const uint32_t ksb = base + 18432;    // K [2][64][72]
    const uint32_t vsb = base + 36864;    // V [2][64][72]

    const int qt  = blockIdx.x;
    const int bh  = blockIdx.y;
    const int tid = threadIdx.x;
    const int w   = tid >> 5;
    const int lane = tid & 31;
    const int l0  = qt * 128;

    const half* __restrict__ Qg = &g_qkv_h[0][bh][l0][0];
    const half* __restrict__ Kg = &g_qkv_h[1][bh][0][0];
    const half* __restrict__ Vg = &g_qkv_h[2][bh][0][0];

    #pragma unroll
    for (int p = 0; p < 4; ++p) {
        int idx = tid + p * 256;
        int r = idx >> 3, q = idx & 7;
        cp16(qsb + r * 144 + q * 16, Qg + (size_t)r * DQ + q * 8);
    }
    #pragma unroll
    for (int p = 0; p < 2; ++p) {
        int idx = tid + p * 256;
        int r = idx >> 3, q = idx & 7;
        cp16(ksb + r * 144 + q * 16, Kg + (size_t)r * DQ + q * 8);
        cp16(vsb + r * 144 + q * 16, Vg + (size_t)r * DQ + q * 8);
    }
    CP_COMMIT();

    const int sub = lane >> 3;
    const uint32_t laneoff =
        (uint32_t)((((sub & 1) * 8) + (lane & 7)) * 144 + (sub >> 1) * 16);

    CP_WAIT0();
    __syncthreads();

    uint32_t qa[4][4];
    #pragma unroll
    for (int kt = 0; kt < 4; ++kt)
        ldsm4(qa[kt], qsb + w * 2304 + kt * 32 + laneoff);

    float oc[8][4];
    #pragma unroll
    for (int nt = 0; nt < 8; ++nt)
        #pragma unroll
        for (int e = 0; e < 4; ++e) oc[nt][e] = 0.0f;
    float Ls0 = 0.0f, Ls1 = 0.0f;

    for (int j = 0; j < NL / 64; ++j) {
        if (j > 0) { CP_WAIT0(); __syncthreads(); }
        if (j + 1 < NL / 64) {
            const uint32_t kd = ksb + ((j + 1) & 1) * 9216;
            const uint32_t vd = vsb + ((j + 1) & 1) * 9216;
            const half* kn = Kg + (size_t)(j + 1) * 64 * DQ;
            const half* vn = Vg + (size_t)(j + 1) * 64 * DQ;
            #pragma unroll
            for (int p = 0; p < 2; ++p) {
                int idx = tid + p * 256;
                int r = idx >> 3, q = idx & 7;
                cp16(kd + r * 144 + q * 16, kn + (size_t)r * DQ + q * 8);
                cp16(vd + r * 144 + q * 16, vn + (size_t)r * DQ + q * 8);
            }
            CP_COMMIT();
        }
        const uint32_t kcb = ksb + (j & 1) * 9216;
        const uint32_t vcb = vsb + (j & 1) * 9216;

        float sc[8][4];
        #pragma unroll
        for (int nt = 0; nt < 8; ++nt)
            #pragma unroll
            for (int e = 0; e < 4; ++e) sc[nt][e] = -SB;
        #pragma unroll
        for (int kt = 0; kt < 4; ++kt) {
            uint32_t kb[4][4];
            #pragma unroll
            for (int ntp = 0; ntp < 4; ++ntp)
                ldsm4(kb[ntp], kcb + ntp * 2304 + kt * 32 + laneoff);
            #pragma unroll
            for (int ntp = 0; ntp < 4; ++ntp) {
                mma16816(sc[2 * ntp],     qa[kt], kb[ntp][0], kb[ntp][2]);
                mma16816(sc[2 * ntp + 1], qa[kt], kb[ntp][1], kb[ntp][3]);
            }
        }

        float l0s = 0.0f, l1s = 0.0f;
        #pragma unroll
        for (int nt = 0; nt < 8; ++nt) {
            sc[nt][0] = exp2f(sc[nt][0]);
            sc[nt][1] = exp2f(sc[nt][1]);
            sc[nt][2] = exp2f(sc[nt][2]);
            sc[nt][3] = exp2f(sc[nt][3]);
            l0s += sc[nt][0] + sc[nt][1];
            l1s += sc[nt][2] + sc[nt][3];
        }
        Ls0 += l0s;
        Ls1 += l1s;

        uint32_t pa[4][4];
        #pragma unroll
        for (int kk = 0; kk < 4; ++kk) {
            pa[kk][0] = pack_h2(sc[2 * kk][0],     sc[2 * kk][1]);
            pa[kk][1] = pack_h2(sc[2 * kk][2],     sc[2 * kk][3]);
            pa[kk][2] = pack_h2(sc[2 * kk + 1][0], sc[2 * kk + 1][1]);
            pa[kk][3] = pack_h2(sc[2 * kk + 1][2], sc[2 * kk + 1][3]);
        }

        #pragma unroll
        for (int kk = 0; kk < 4; ++kk) {
            uint32_t vb[4][4];
            #pragma unroll
            for (int ntp = 0; ntp < 4; ++ntp)
                ldsm4t(vb[ntp], vcb + kk * 2304 + ntp * 32 + laneoff);
            #pragma unroll
            for (int ntp = 0; ntp < 4; ++ntp) {
                mma16816(oc[2 * ntp],     pa[kk], vb[ntp][0], vb[ntp][1]);
                mma16816(oc[2 * ntp + 1], pa[kk], vb[ntp][2], vb[ntp][3]);
            }
        }
    }

    Ls0 += __shfl_xor_sync(0xffffffffu, Ls0, 1);
    Ls0 += __shfl_xor_sync(0xffffffffu, Ls0, 2);
    Ls1 += __shfl_xor_sync(0xffffffffu, Ls1, 1);
    Ls1 += __shfl_xor_sync(0xffffffffu, Ls1, 2);
    const float inv0 = 1.0f / Ls0;
    const float inv1 = 1.0f / Ls1;

    const int b = bh >> 4, h = bh & 15;
    const int g = lane >> 2, cq = lane & 3;
    half* p0 = g_att_h + (size_t)(b * NL + l0 + w * 16 + g) * DM + h * DQ + 2 * cq;
    half* p1 = p0 + (size_t)8 * DM;
    #pragma unroll
    for (int nt = 0; nt < 8; ++nt) {
        half2 v0 = __floats2half2_rn(oc[nt][0] * inv0, oc[nt][1] * inv0);
        half2 v1 = __floats2half2_rn(oc[nt][2] * inv1, oc[nt][3] * inv1);
        *(half2*)(p0 + nt * 8) = v0;
        *(half2*)(p1 + nt * 8) = v1;
    }
}

// ---------------------------------------------------------------------------
// Kernel 4: residual + LayerNorm. One block per row.
// ---------------------------------------------------------------------------
__global__ __launch_bounds__(256) void ln_kernel(
    const float* __restrict__ x,
    const float* __restrict__ gamma,
    const float* __restrict__ beta,
    float* __restrict__ out)
{
    const int r   = blockIdx.x;
    const int tid = threadIdx.x;
    const int lane = tid & 31, wid = tid >> 5;

    float y[4];
    float s = 0.0f, s2 = 0.0f;
    #pragma unroll
    for (int k = 0; k < 4; ++k) {
        int cc = tid + k * 256;
        float v = x[(size_t)r * DM + cc] + g_proj[r][cc];
        y[k] = v;
        s  += v;
        s2 += v * v;
    }
    #pragma unroll
    for (int o = 16; o; o >>= 1) {
        s  += __shfl_xor_sync(0xffffffffu, s, o);
        s2 += __shfl_xor_sync(0xffffffffu, s2, o);
    }
    __shared__ float rs[8], rs2[8];
    if (lane == 0) { rs[wid] = s; rs2[wid] = s2; }
    __syncthreads();
    float tot = 0.0f, tot2 = 0.0f;
    #pragma unroll
    for (int i = 0; i < 8; ++i) { tot += rs[i]; tot2 += rs2[i]; }

    const float mu   = tot * (1.0f / DM);
    const float var  = tot2 * (1.0f / DM) - mu * mu;
    const float rstd = rsqrtf(var + LN_EPS);

    #pragma unroll
    for (int k = 0; k < 4; ++k) {
        int cc = tid + k * 256;
        out[(size_t)r * DM + cc] = (y[k] - mu) * rstd * gamma[cc] + beta[cc];
    }
}

// ---------------------------------------------------------------------------
extern "C" void kernel_launch(void* const* d_in, const int* in_sizes, int n_in,
                              void* d_out, int out_size)
{
    (void)in_sizes; (void)n_in; (void)out_size;
    const float* x     = (const float*)d_in[0];
    const float* wq    = (const float*)d_in[1];
    const float* wk    = (const float*)d_in[2];
    const float* wv    = (const float*)d_in[3];
    const float* wo    = (const float*)d_in[4];
    const float* gamma = (const float*)d_in[5];
    const float* beta  = (const float*)d_in[6];
    float* out = (float*)d_out;

    cudaFuncSetAttribute(gemm_kernel, cudaFuncAttributeMaxDynamicSharedMemorySize, GEMM_SMEM);
    cudaFuncSetAttribute(attn_kernel, cudaFuncAttributeMaxDynamicSharedMemorySize, ATT_SMEM);

    prep_x_kernel<<<ROWS * DM / 1024, 256>>>(x);
    prep_wqkv_kernel<<<dim3(2, 32, 48), dim3(32, 8)>>>(wq, wk, wv);
    prep_wo_kernel<<<dim3(32, 32), dim3(32, 8)>>>(wo);
    gemm_kernel<<<dim3(ROWS / 128, 24), 128, GEMM_SMEM>>>(0);   // QKV projection
    attn_kernel<<<dim3(NL / 128, NB * NH), 256, ATT_SMEM>>>();
    gemm_kernel<<<dim3(ROWS / 128, 8), 128, GEMM_SMEM>>>(1);    // output projection
    ln_kernel<<<ROWS, 256>>>(x, gamma, beta, out);
}